// round 1
// baseline (speedup 1.0000x reference)
#include <cuda_runtime.h>
#include <math.h>

#define NB 64           // batch
#define NN 2048         // nodes
#define NC 64           // channels (in == out)
#define ND 10           // embedding dim
#define NJ (NB * NC)    // 4096 flattened (b,c)
#define KI 192          // cheb_k * C_IN

// ---- scratch (device globals; no runtime allocation allowed) ----
__device__ float g_S [NN * NN];            // supports, 16.8 MB
__device__ float g_Xt[NN * NJ];            // x transposed to [m, b*64+c], 33.6 MB
__device__ float g_Y1[NN * NJ];            // S @ Xt
__device__ float g_Y2[NN * NJ];            // S @ Y1
__device__ float g_W [(size_t)NN * KI * NC]; // per-node weights, 100 MB

// ============================================================
// Kernel A: S[n,:] = softmax(relu(E[n]·E[m]))  (row softmax)
// ============================================================
__global__ __launch_bounds__(256) void supports_kernel(const float* __restrict__ E) {
    __shared__ float vals[NN];
    __shared__ float red[256];
    const int n = blockIdx.x;
    const int tid = threadIdx.x;

    float en[ND];
#pragma unroll
    for (int d = 0; d < ND; d++) en[d] = E[n * ND + d];

    float lmax = -1e30f;
    for (int m = tid; m < NN; m += 256) {
        float v = 0.f;
#pragma unroll
        for (int d = 0; d < ND; d++) v = fmaf(en[d], E[m * ND + d], v);
        v = fmaxf(v, 0.f);
        vals[m] = v;
        lmax = fmaxf(lmax, v);
    }
    red[tid] = lmax;
    __syncthreads();
    for (int s = 128; s > 0; s >>= 1) {
        if (tid < s) red[tid] = fmaxf(red[tid], red[tid + s]);
        __syncthreads();
    }
    const float gmax = red[0];
    __syncthreads();

    float lsum = 0.f;
    for (int m = tid; m < NN; m += 256) {
        float e = expf(vals[m] - gmax);
        vals[m] = e;
        lsum += e;
    }
    red[tid] = lsum;
    __syncthreads();
    for (int s = 128; s > 0; s >>= 1) {
        if (tid < s) red[tid] += red[tid + s];
        __syncthreads();
    }
    const float inv = 1.f / red[0];
    for (int m = tid; m < NN; m += 256)
        g_S[n * NN + m] = vals[m] * inv;
}

// ============================================================
// Kernel T: Xt[m, b*64+c] = x[b, m, c]
// ============================================================
__global__ __launch_bounds__(256) void transpose_kernel(const float* __restrict__ x) {
    const int idx = blockIdx.x * 256 + threadIdx.x;   // b*2^17 + m*64 + c
    const int c = idx & 63;
    const int m = (idx >> 6) & 2047;
    const int b = idx >> 17;
    g_Xt[m * NJ + b * NC + c] = x[idx];
}

// ============================================================
// Kernel W: W[n, ki, o] = sum_d E[n,d] * Wp[d, ki, o]
//   block: 16 nodes x 256 contiguous elements e = ki*64+o
// ============================================================
__global__ __launch_bounds__(256) void weights_kernel(const float* __restrict__ E,
                                                      const float* __restrict__ Wp) {
    __shared__ float Es[16][ND];
    const int e0 = blockIdx.x * 256;       // 48 tiles over 12288
    const int n0 = blockIdx.y * 16;        // 128 tiles over 2048
    const int tid = threadIdx.x;
    if (tid < 16 * ND) Es[tid / ND][tid % ND] = E[(n0 + tid / ND) * ND + (tid % ND)];
    __syncthreads();

    const int e = e0 + tid;
    float wp[ND];
#pragma unroll
    for (int d = 0; d < ND; d++) wp[d] = Wp[d * (KI * NC) + e];
#pragma unroll
    for (int nn = 0; nn < 16; nn++) {
        float acc = 0.f;
#pragma unroll
        for (int d = 0; d < ND; d++) acc = fmaf(Es[nn][d], wp[d], acc);
        g_W[(size_t)(n0 + nn) * (KI * NC) + e] = acc;
    }
}

// ============================================================
// Kernel G: C = A(MxK) @ B(KxN), row-major, 128x128x8 tile, 8x8/thread
// ============================================================
__device__ __forceinline__ void sgemm_body(const float* __restrict__ A,
                                           const float* __restrict__ B,
                                           float* __restrict__ C,
                                           int M, int N, int Kd) {
    __shared__ float As[8][128];
    __shared__ float Bs[8][128];
    const int tid = threadIdx.x;
    const int tx = tid % 16;        // n direction
    const int ty = tid / 16;        // m direction
    const int bm = blockIdx.y * 128;
    const int bn = blockIdx.x * 128;

    const int arow = tid >> 1;            // 0..127
    const int acol = (tid & 1) * 4;       // 0 or 4
    const int brow = tid >> 5;            // 0..7
    const int bcol = (tid & 31) * 4;      // 0..124

    float acc[8][8] = {};

    for (int k0 = 0; k0 < Kd; k0 += 8) {
        const float4 a = *(const float4*)&A[(size_t)(bm + arow) * Kd + k0 + acol];
        const float4 b = *(const float4*)&B[(size_t)(k0 + brow) * N + bn + bcol];
        __syncthreads();
        As[acol + 0][arow] = a.x;
        As[acol + 1][arow] = a.y;
        As[acol + 2][arow] = a.z;
        As[acol + 3][arow] = a.w;
        *(float4*)&Bs[brow][bcol] = b;
        __syncthreads();
#pragma unroll
        for (int kk = 0; kk < 8; kk++) {
            float ra[8], rb[8];
            *(float4*)&ra[0] = *(const float4*)&As[kk][ty * 8];
            *(float4*)&ra[4] = *(const float4*)&As[kk][ty * 8 + 4];
            *(float4*)&rb[0] = *(const float4*)&Bs[kk][tx * 8];
            *(float4*)&rb[4] = *(const float4*)&Bs[kk][tx * 8 + 4];
#pragma unroll
            for (int i = 0; i < 8; i++)
#pragma unroll
                for (int j = 0; j < 8; j++)
                    acc[i][j] = fmaf(ra[i], rb[j], acc[i][j]);
        }
    }
#pragma unroll
    for (int i = 0; i < 8; i++) {
        float4 v0 = make_float4(acc[i][0], acc[i][1], acc[i][2], acc[i][3]);
        float4 v1 = make_float4(acc[i][4], acc[i][5], acc[i][6], acc[i][7]);
        float* crow = &C[(size_t)(bm + ty * 8 + i) * N + bn + tx * 8];
        *(float4*)crow = v0;
        *(float4*)(crow + 4) = v1;
    }
}

__global__ __launch_bounds__(256) void sgemm_y1_kernel() {
    sgemm_body(g_S, g_Xt, g_Y1, NN, NJ, NN);
}
__global__ __launch_bounds__(256) void sgemm_y2_kernel() {
    sgemm_body(g_S, g_Y1, g_Y2, NN, NJ, NN);
}

// ============================================================
// Kernel D: per node n (block): out[b,n,o] = A_n[b, ki] @ W_n[ki, o] + bias_n[o]
//   A_n[b, k*64+i] = { x[b,n,i], Y1[n, b*64+i], 2*Y2[n, b*64+i] - x[b,n,i] }
//   smem: As [192][65] (padded), Ws [192][64]
// ============================================================
__global__ __launch_bounds__(256) void output_kernel(const float* __restrict__ x,
                                                     const float* __restrict__ E,
                                                     const float* __restrict__ bp,
                                                     float* __restrict__ out) {
    extern __shared__ float sm[];
    float* As = sm;                 // 192 * 65 = 12480 floats
    float* Ws = sm + KI * 65;       // 192 * 64 = 12288 floats

    const int n = blockIdx.x;
    const int tid = threadIdx.x;

    // fill A (layout [ki][b], pitch 65 -> conflict-free stores)
    for (int idx = tid; idx < NJ; idx += 256) {
        const int b = idx >> 6;
        const int i = idx & 63;
        const float xv = x[(size_t)b * (NN * NC) + n * NC + i];
        const float y1 = g_Y1[(size_t)n * NJ + idx];
        const float y2 = g_Y2[(size_t)n * NJ + idx];
        As[(i)        * 65 + b] = xv;
        As[(64 + i)   * 65 + b] = y1;
        As[(128 + i)  * 65 + b] = 2.f * y2 - xv;
    }
    // fill W (straight coalesced copy)
    const float* Wrow = &g_W[(size_t)n * (KI * NC)];
    for (int idx = tid * 4; idx < KI * NC; idx += 1024)
        *(float4*)&Ws[idx] = *(const float4*)&Wrow[idx];
    __syncthreads();

    const int o0 = (tid % 16) * 4;
    const int b0 = (tid / 16) * 4;
    float acc[4][4] = {};
#pragma unroll 4
    for (int kk = 0; kk < KI; kk++) {
        const float a0 = As[kk * 65 + b0 + 0];
        const float a1 = As[kk * 65 + b0 + 1];
        const float a2 = As[kk * 65 + b0 + 2];
        const float a3 = As[kk * 65 + b0 + 3];
        const float4 w = *(const float4*)&Ws[kk * 64 + o0];
        acc[0][0] = fmaf(a0, w.x, acc[0][0]); acc[0][1] = fmaf(a0, w.y, acc[0][1]);
        acc[0][2] = fmaf(a0, w.z, acc[0][2]); acc[0][3] = fmaf(a0, w.w, acc[0][3]);
        acc[1][0] = fmaf(a1, w.x, acc[1][0]); acc[1][1] = fmaf(a1, w.y, acc[1][1]);
        acc[1][2] = fmaf(a1, w.z, acc[1][2]); acc[1][3] = fmaf(a1, w.w, acc[1][3]);
        acc[2][0] = fmaf(a2, w.x, acc[2][0]); acc[2][1] = fmaf(a2, w.y, acc[2][1]);
        acc[2][2] = fmaf(a2, w.z, acc[2][2]); acc[2][3] = fmaf(a2, w.w, acc[2][3]);
        acc[3][0] = fmaf(a3, w.x, acc[3][0]); acc[3][1] = fmaf(a3, w.y, acc[3][1]);
        acc[3][2] = fmaf(a3, w.z, acc[3][2]); acc[3][3] = fmaf(a3, w.w, acc[3][3]);
    }

    // bias for this thread's 4 output channels
    float bias[4];
#pragma unroll
    for (int oo = 0; oo < 4; oo++) {
        float s = 0.f;
#pragma unroll
        for (int d = 0; d < ND; d++) s = fmaf(E[n * ND + d], bp[d * NC + o0 + oo], s);
        bias[oo] = s;
    }

#pragma unroll
    for (int bb = 0; bb < 4; bb++) {
        float4 v = make_float4(acc[bb][0] + bias[0], acc[bb][1] + bias[1],
                               acc[bb][2] + bias[2], acc[bb][3] + bias[3]);
        *(float4*)&out[(size_t)(b0 + bb) * (NN * NC) + n * NC + o0] = v;
    }
}

// ============================================================
extern "C" void kernel_launch(void* const* d_in, const int* in_sizes, int n_in,
                              void* d_out, int out_size) {
    (void)in_sizes; (void)n_in; (void)out_size;
    const float* x  = (const float*)d_in[0];   // [64, 2048, 64]
    const float* E  = (const float*)d_in[1];   // [2048, 10]
    const float* Wp = (const float*)d_in[2];   // [10, 3, 64, 64]
    const float* bp = (const float*)d_in[3];   // [10, 64]
    float* out = (float*)d_out;                // [64, 2048, 64]

    static const int kOutSmem = (KI * 65 + KI * NC) * (int)sizeof(float);  // 99072 B
    cudaFuncSetAttribute(output_kernel, cudaFuncAttributeMaxDynamicSharedMemorySize, kOutSmem);

    supports_kernel<<<NN, 256>>>(E);
    transpose_kernel<<<(NB * NN * NC) / 256, 256>>>(x);
    weights_kernel<<<dim3((KI * NC) / 256, NN / 16), 256>>>(E, Wp);

    dim3 ggrid(NJ / 128, NN / 128);   // (32, 16)
    sgemm_y1_kernel<<<ggrid, 256>>>();
    sgemm_y2_kernel<<<ggrid, 256>>>();

    output_kernel<<<NN, 256, kOutSmem>>>(x, E, bp, out);
}

// round 3
// speedup vs baseline: 1.4955x; 1.4955x over previous
#include <cuda_runtime.h>
#include <math.h>
#include <stdint.h>

#define NB 64
#define NN 2048
#define NC 64
#define ND 10
#define NJ 4096          // NB*NC
#define KI 192           // cheb_k * C_IN

// ------------------ scratch (static device globals) ------------------
__device__ float g_Shi [NN * NN];
__device__ float g_Slo [NN * NN];
__device__ float g_Xqhi[(size_t)NJ * NN];   // [j][m]
__device__ float g_Xqlo[(size_t)NJ * NN];
__device__ float g_Y1qhi[(size_t)NJ * NN];  // [j][m]
__device__ float g_Y1qlo[(size_t)NJ * NN];
__device__ float g_Y1nm[(size_t)NN * NJ];   // [n][j]
__device__ float g_Y2nm[(size_t)NN * NJ];
__device__ float g_W   [(size_t)NN * KI * NC];

// ------------------ helpers ------------------
__device__ __forceinline__ uint32_t smem_u32(const void* p) {
    uint32_t a;
    asm("{ .reg .u64 t; cvta.to.shared.u64 t, %1; cvt.u32.u64 %0, t; }" : "=r"(a) : "l"(p));
    return a;
}
__device__ __forceinline__ float tf32r(float x) {
    uint32_t u; asm("cvt.rna.tf32.f32 %0, %1;" : "=r"(u) : "f"(x));
    return __uint_as_float(u);
}
__device__ __forceinline__ void cpa16(uint32_t s, const void* g) {
    asm volatile("cp.async.cg.shared.global [%0], [%1], 16;" :: "r"(s), "l"(g));
}

#define LDSM4(r, a) \
    asm volatile("ldmatrix.sync.aligned.m8n8.x4.shared.b16 {%0,%1,%2,%3}, [%4];" \
        : "=r"((r)[0]), "=r"((r)[1]), "=r"((r)[2]), "=r"((r)[3]) : "r"(a))

#define MMA_TF32(c, a, b0, b1) \
    asm volatile("mma.sync.aligned.m16n8k8.row.col.f32.tf32.tf32.f32 " \
        "{%0,%1,%2,%3}, {%4,%5,%6,%7}, {%8,%9}, {%0,%1,%2,%3};" \
        : "+f"((c)[0]), "+f"((c)[1]), "+f"((c)[2]), "+f"((c)[3]) \
        : "r"((a)[0]), "r"((a)[1]), "r"((a)[2]), "r"((a)[3]), "r"(b0), "r"(b1))

// ============================================================
// supports: S[n,:] = softmax(relu(E[n]·E[m])), split tf32 hi/lo
// ============================================================
__global__ __launch_bounds__(256) void supports_kernel(const float* __restrict__ E) {
    __shared__ float vals[NN];
    __shared__ float red[256];
    const int n = blockIdx.x;
    const int tid = threadIdx.x;

    float en[ND];
#pragma unroll
    for (int d = 0; d < ND; d++) en[d] = E[n * ND + d];

    float lmax = -1e30f;
    for (int m = tid; m < NN; m += 256) {
        float v = 0.f;
#pragma unroll
        for (int d = 0; d < ND; d++) v = fmaf(en[d], E[m * ND + d], v);
        v = fmaxf(v, 0.f);
        vals[m] = v;
        lmax = fmaxf(lmax, v);
    }
    red[tid] = lmax; __syncthreads();
    for (int s = 128; s > 0; s >>= 1) { if (tid < s) red[tid] = fmaxf(red[tid], red[tid + s]); __syncthreads(); }
    const float gmax = red[0]; __syncthreads();

    float lsum = 0.f;
    for (int m = tid; m < NN; m += 256) {
        float e = expf(vals[m] - gmax);
        vals[m] = e; lsum += e;
    }
    red[tid] = lsum; __syncthreads();
    for (int s = 128; s > 0; s >>= 1) { if (tid < s) red[tid] += red[tid + s]; __syncthreads(); }
    const float inv = 1.f / red[0];
    for (int m = tid; m < NN; m += 256) {
        float v = vals[m] * inv;
        float hi = tf32r(v);
        g_Shi[n * NN + m] = hi;
        g_Slo[n * NN + m] = tf32r(v - hi);
    }
}

// ============================================================
// Xq builder: Xq[j = b*64+c][m] = x[b][m][c], split hi/lo
// ============================================================
__global__ __launch_bounds__(256) void xq_kernel(const float* __restrict__ x) {
    __shared__ float sm[64 * 33];
    const int m0 = blockIdx.x * 32;
    const int b  = blockIdx.y;
    const int t  = threadIdx.x;
#pragma unroll
    for (int p = 0; p < 8; p++) {
        int e = t + 256 * p;
        int r = e >> 6, c = e & 63;
        sm[c * 33 + r] = x[(size_t)b * (NN * NC) + (size_t)(m0 + r) * NC + c];
    }
    __syncthreads();
#pragma unroll
    for (int p = 0; p < 8; p++) {
        int e = t + 256 * p;
        int c = e >> 5, r = e & 31;
        float v = sm[c * 33 + r];
        float hi = tf32r(v);
        size_t off = (size_t)(b * 64 + c) * NN + m0 + r;
        g_Xqhi[off] = hi;
        g_Xqlo[off] = tf32r(v - hi);
    }
}

// ============================================================
// weights: W[n, ki, o] = sum_d E[n,d] * Wp[d, ki, o]
// ============================================================
__global__ __launch_bounds__(256) void weights_kernel(const float* __restrict__ E,
                                                      const float* __restrict__ Wp) {
    __shared__ float Es[16][ND];
    const int e0 = blockIdx.x * 256;
    const int n0 = blockIdx.y * 16;
    const int tid = threadIdx.x;
    if (tid < 16 * ND) Es[tid / ND][tid % ND] = E[(n0 + tid / ND) * ND + (tid % ND)];
    __syncthreads();
    const int e = e0 + tid;
    float wp[ND];
#pragma unroll
    for (int d = 0; d < ND; d++) wp[d] = Wp[d * (KI * NC) + e];
#pragma unroll
    for (int nn = 0; nn < 16; nn++) {
        float acc = 0.f;
#pragma unroll
        for (int d = 0; d < ND; d++) acc = fmaf(Es[nn][d], wp[d], acc);
        g_W[(size_t)(n0 + nn) * (KI * NC) + e] = acc;
    }
}

// ============================================================
// 3xTF32 mma.sync GEMM: C[128x128] tile, K=2048, 3-stage cp.async.
//   A = S hi/lo ([n][m], K-major).  B = Xq or Y1q hi/lo ([j][m], K-major).
//   MODE 1: C -> Y1nm [n][j]  +  Y1q hi/lo [j][n] (transposed via smem)
//   MODE 2: C -> Y2nm [n][j]
// ============================================================
#define STAGE_BYTES 65536
#define AHI_OFF 0
#define ALO_OFF 16384
#define BHI_OFF 32768
#define BLO_OFF 49152
#define GEMM_SMEM (3 * STAGE_BYTES)
#define NITER (NN / 32)   // 64

template <int MODE>
__global__ void __launch_bounds__(256, 1) gemm_tf32x3_kernel() {
    extern __shared__ float dsm[];
    const int t = threadIdx.x;
    const int l = t & 31;
    const int wid = t >> 5;
    const int wm = wid >> 2;       // 0..1  (m direction, 64 rows each)
    const int wn = wid & 3;        // 0..3  (n direction, 32 cols each)
    const int bm = blockIdx.y * 128;
    const int bn = blockIdx.x * 128;

    const float* Ah = g_Shi + (size_t)bm * NN;
    const float* Al = g_Slo + (size_t)bm * NN;
    const float* Bh = (MODE == 1 ? g_Xqhi : g_Y1qhi) + (size_t)bn * NN;
    const float* Bl = (MODE == 1 ? g_Xqlo : g_Y1qlo) + (size_t)bn * NN;

    const uint32_t sb0 = smem_u32(dsm);

    auto load_stage = [&](int s, int k0) {
        const uint32_t sb = sb0 + (uint32_t)s * STAGE_BYTES;
#pragma unroll
        for (int p = 0; p < 4; p++) {
            const int g = t + 256 * p;          // granule id (16B)
            const int row = g >> 3;
            const int c16 = g & 7;
            const int sw = c16 ^ (row & 7);     // XOR swizzle on 16B columns
            const uint32_t so = sb + (uint32_t)(row * 128 + sw * 16);
            const size_t go = (size_t)row * NN + k0 + c16 * 4;
            cpa16(so + AHI_OFF, Ah + go);
            cpa16(so + ALO_OFF, Al + go);
            cpa16(so + BHI_OFF, Bh + go);
            cpa16(so + BLO_OFF, Bl + go);
        }
        asm volatile("cp.async.commit_group;" ::: "memory");
    };

    float acc[4][4][4];
#pragma unroll
    for (int a = 0; a < 4; a++)
#pragma unroll
        for (int b = 0; b < 4; b++)
#pragma unroll
            for (int c = 0; c < 4; c++) acc[a][b][c] = 0.f;

    // ldmatrix lane geometry
    const int t4 = l >> 3;                       // subtile id 0..3
    const int l7 = l & 7;
    const int arow_in = ((t4 & 1) << 3) + l7;    // A: subtile row-group + row
    const int brow_in = ((t4 >> 1) << 3) + l7;   // B: subtile n-group + row
    const uint32_t abase = (uint32_t)((wm * 64 + arow_in) * 128);
    const uint32_t bbase = (uint32_t)((wn * 32 + brow_in) * 128);
    const int akg = t4 >> 1;                     // A k-group select within kstep
    const int bkg = t4 & 1;                      // B k-group select within kstep

    load_stage(0, 0);
    load_stage(1, 32);

    for (int i = 0; i < NITER; i++) {
        asm volatile("cp.async.wait_group 1;" ::: "memory");
        __syncthreads();
        if (i + 2 < NITER) load_stage((i + 2) % 3, (i + 2) * 32);
        const uint32_t sb = sb0 + (uint32_t)(i % 3) * STAGE_BYTES;
#pragma unroll
        for (int ks = 0; ks < 4; ks++) {
            const uint32_t xa = (uint32_t)(((ks * 2 + akg) ^ l7) << 4);
            const uint32_t xb = (uint32_t)(((ks * 2 + bkg) ^ l7) << 4);
            uint32_t ah[4][4], al[4][4];
#pragma unroll
            for (int mt = 0; mt < 4; mt++) {
                const uint32_t ad = sb + abase + (uint32_t)(mt * 16 * 128) + xa;
                LDSM4(ah[mt], ad + AHI_OFF);
                LDSM4(al[mt], ad + ALO_OFF);
            }
            uint32_t bhf[2][4], blf[2][4];
#pragma unroll
            for (int nh = 0; nh < 2; nh++) {
                const uint32_t bd = sb + bbase + (uint32_t)(nh * 16 * 128) + xb;
                LDSM4(bhf[nh], bd + BHI_OFF);
                LDSM4(blf[nh], bd + BLO_OFF);
            }
#pragma unroll
            for (int mt = 0; mt < 4; mt++) {
#pragma unroll
                for (int n8 = 0; n8 < 4; n8++) {
                    const int nh = n8 >> 1;
                    const int q = (n8 & 1) * 2;
                    MMA_TF32(acc[mt][n8], ah[mt], bhf[nh][q], bhf[nh][q + 1]);
                    MMA_TF32(acc[mt][n8], al[mt], bhf[nh][q], bhf[nh][q + 1]);
                    MMA_TF32(acc[mt][n8], ah[mt], blf[nh][q], blf[nh][q + 1]);
                }
            }
        }
    }

    // ---------------- epilogue ----------------
    float* Ynm = (MODE == 1) ? g_Y1nm : g_Y2nm;
    const int lm = l >> 2;
    const int lc = (l & 3) << 1;
#pragma unroll
    for (int mt = 0; mt < 4; mt++)
#pragma unroll
        for (int n8 = 0; n8 < 4; n8++) {
            const int r = bm + wm * 64 + mt * 16 + lm;
            const int col = bn + wn * 32 + n8 * 8 + lc;
            *(float2*)&Ynm[(size_t)r * NJ + col] =
                make_float2(acc[mt][n8][0], acc[mt][n8][1]);
            *(float2*)&Ynm[(size_t)(r + 8) * NJ + col] =
                make_float2(acc[mt][n8][2], acc[mt][n8][3]);
        }

    if (MODE == 1) {
        // transpose tile via smem (pitch 132), then coalesced hi/lo stores
        __syncthreads();
#pragma unroll
        for (int mt = 0; mt < 4; mt++)
#pragma unroll
            for (int n8 = 0; n8 < 4; n8++) {
                const int jl = wn * 32 + n8 * 8 + lc;
                const int ml = wm * 64 + mt * 16 + lm;
                dsm[jl * 132 + ml]           = acc[mt][n8][0];
                dsm[(jl + 1) * 132 + ml]     = acc[mt][n8][1];
                dsm[jl * 132 + ml + 8]       = acc[mt][n8][2];
                dsm[(jl + 1) * 132 + ml + 8] = acc[mt][n8][3];
            }
        __syncthreads();
#pragma unroll
        for (int it = 0; it < 16; it++) {
            const int j = wid * 16 + it;
            const int m4 = l * 4;
            const float4 v = *(const float4*)&dsm[j * 132 + m4];
            float4 hi, lo;
            hi.x = tf32r(v.x); lo.x = tf32r(v.x - hi.x);
            hi.y = tf32r(v.y); lo.y = tf32r(v.y - hi.y);
            hi.z = tf32r(v.z); lo.z = tf32r(v.z - hi.z);
            hi.w = tf32r(v.w); lo.w = tf32r(v.w - hi.w);
            const size_t off = (size_t)(bn + j) * NN + bm + m4;
            *(float4*)&g_Y1qhi[off] = hi;
            *(float4*)&g_Y1qlo[off] = lo;
        }
    }
}

// ============================================================
// output: per node n, out[b,n,o] = A_n[b,ki] @ W_n[ki,o] + bias_n[o]
// ============================================================
__global__ __launch_bounds__(256) void output_kernel(const float* __restrict__ x,
                                                     const float* __restrict__ E,
                                                     const float* __restrict__ bp,
                                                     float* __restrict__ out) {
    extern __shared__ float sm[];
    float* As = sm;                 // 192 * 65
    float* Ws = sm + KI * 65;       // 192 * 64

    const int n = blockIdx.x;
    const int tid = threadIdx.x;

    for (int idx = tid; idx < NJ; idx += 256) {
        const int b = idx >> 6;
        const int i = idx & 63;
        const float xv = x[(size_t)b * (NN * NC) + n * NC + i];
        const float y1 = g_Y1nm[(size_t)n * NJ + idx];
        const float y2 = g_Y2nm[(size_t)n * NJ + idx];
        As[(i)       * 65 + b] = xv;
        As[(64 + i)  * 65 + b] = y1;
        As[(128 + i) * 65 + b] = 2.f * y2 - xv;
    }
    const float* Wrow = &g_W[(size_t)n * (KI * NC)];
    for (int idx = tid * 4; idx < KI * NC; idx += 1024)
        *(float4*)&Ws[idx] = *(const float4*)&Wrow[idx];
    __syncthreads();

    const int o0 = (tid % 16) * 4;
    const int b0 = (tid / 16) * 4;
    float acc[4][4] = {};
#pragma unroll 4
    for (int kk = 0; kk < KI; kk++) {
        const float a0 = As[kk * 65 + b0 + 0];
        const float a1 = As[kk * 65 + b0 + 1];
        const float a2 = As[kk * 65 + b0 + 2];
        const float a3 = As[kk * 65 + b0 + 3];
        const float4 w = *(const float4*)&Ws[kk * 64 + o0];
        acc[0][0] = fmaf(a0, w.x, acc[0][0]); acc[0][1] = fmaf(a0, w.y, acc[0][1]);
        acc[0][2] = fmaf(a0, w.z, acc[0][2]); acc[0][3] = fmaf(a0, w.w, acc[0][3]);
        acc[1][0] = fmaf(a1, w.x, acc[1][0]); acc[1][1] = fmaf(a1, w.y, acc[1][1]);
        acc[1][2] = fmaf(a1, w.z, acc[1][2]); acc[1][3] = fmaf(a1, w.w, acc[1][3]);
        acc[2][0] = fmaf(a2, w.x, acc[2][0]); acc[2][1] = fmaf(a2, w.y, acc[2][1]);
        acc[2][2] = fmaf(a2, w.z, acc[2][2]); acc[2][3] = fmaf(a2, w.w, acc[2][3]);
        acc[3][0] = fmaf(a3, w.x, acc[3][0]); acc[3][1] = fmaf(a3, w.y, acc[3][1]);
        acc[3][2] = fmaf(a3, w.z, acc[3][2]); acc[3][3] = fmaf(a3, w.w, acc[3][3]);
    }

    float bias[4];
#pragma unroll
    for (int oo = 0; oo < 4; oo++) {
        float s = 0.f;
#pragma unroll
        for (int d = 0; d < ND; d++) s = fmaf(E[n * ND + d], bp[d * NC + o0 + oo], s);
        bias[oo] = s;
    }

#pragma unroll
    for (int bb = 0; bb < 4; bb++) {
        float4 v = make_float4(acc[bb][0] + bias[0], acc[bb][1] + bias[1],
                               acc[bb][2] + bias[2], acc[bb][3] + bias[3]);
        *(float4*)&out[(size_t)(b0 + bb) * (NN * NC) + n * NC + o0] = v;
    }
}

// ============================================================
extern "C" void kernel_launch(void* const* d_in, const int* in_sizes, int n_in,
                              void* d_out, int out_size) {
    (void)in_sizes; (void)n_in; (void)out_size;
    const float* x  = (const float*)d_in[0];
    const float* E  = (const float*)d_in[1];
    const float* Wp = (const float*)d_in[2];
    const float* bp = (const float*)d_in[3];
    float* out = (float*)d_out;

    const int kOutSmem = (KI * 65 + KI * NC) * (int)sizeof(float);
    cudaFuncSetAttribute(output_kernel, cudaFuncAttributeMaxDynamicSharedMemorySize, kOutSmem);
    cudaFuncSetAttribute(gemm_tf32x3_kernel<1>, cudaFuncAttributeMaxDynamicSharedMemorySize, GEMM_SMEM);
    cudaFuncSetAttribute(gemm_tf32x3_kernel<2>, cudaFuncAttributeMaxDynamicSharedMemorySize, GEMM_SMEM);

    supports_kernel<<<NN, 256>>>(E);
    xq_kernel<<<dim3(NN / 32, NB), 256>>>(x);
    weights_kernel<<<dim3((KI * NC) / 256, NN / 16), 256>>>(E, Wp);

    dim3 ggrid(NJ / 128, NN / 128);   // (32, 16)
    gemm_tf32x3_kernel<1><<<ggrid, 256, GEMM_SMEM>>>();
    gemm_tf32x3_kernel<2><<<ggrid, 256, GEMM_SMEM>>>();

    output_kernel<<<NN, 256, kOutSmem>>>(x, E, bp, out);
}

// round 4
// speedup vs baseline: 1.5102x; 1.0098x over previous
#include <cuda_runtime.h>
#include <math.h>
#include <stdint.h>

#define NB 64
#define NN 2048
#define NC 64
#define ND 10
#define NJ 4096          // NB*NC
#define KI 192           // cheb_k * C_IN

// ------------------ scratch (static device globals) ------------------
__device__ float g_Shi [NN * NN];
__device__ float g_Slo [NN * NN];
__device__ float g_Xqhi[(size_t)NJ * NN];   // [j][m]
__device__ float g_Xqlo[(size_t)NJ * NN];
__device__ float g_Y1qhi[(size_t)NJ * NN];  // [j][m]
__device__ float g_Y1qlo[(size_t)NJ * NN];
__device__ float g_Y1nm[(size_t)NN * NJ];   // [n][j]
__device__ float g_Y2nm[(size_t)NN * NJ];
__device__ float g_W   [(size_t)NN * KI * NC];

// ------------------ helpers ------------------
__device__ __forceinline__ uint32_t smem_u32(const void* p) {
    uint32_t a;
    asm("{ .reg .u64 t; cvta.to.shared.u64 t, %1; cvt.u32.u64 %0, t; }" : "=r"(a) : "l"(p));
    return a;
}
__device__ __forceinline__ float tf32r(float x) {
    uint32_t u; asm("cvt.rna.tf32.f32 %0, %1;" : "=r"(u) : "f"(x));
    return __uint_as_float(u);
}
__device__ __forceinline__ void cpa16(uint32_t s, const void* g) {
    asm volatile("cp.async.cg.shared.global [%0], [%1], 16;" :: "r"(s), "l"(g));
}

#define LDSM4(r, a) \
    asm volatile("ldmatrix.sync.aligned.m8n8.x4.shared.b16 {%0,%1,%2,%3}, [%4];" \
        : "=r"((r)[0]), "=r"((r)[1]), "=r"((r)[2]), "=r"((r)[3]) : "r"(a))

#define MMA_TF32(c, a, b0, b1) \
    asm volatile("mma.sync.aligned.m16n8k8.row.col.f32.tf32.tf32.f32 " \
        "{%0,%1,%2,%3}, {%4,%5,%6,%7}, {%8,%9}, {%0,%1,%2,%3};" \
        : "+f"((c)[0]), "+f"((c)[1]), "+f"((c)[2]), "+f"((c)[3]) \
        : "r"((a)[0]), "r"((a)[1]), "r"((a)[2]), "r"((a)[3]), "r"(b0), "r"(b1))

// ============================================================
// supports: S[n,:] = softmax(relu(E[n]·E[m])), split tf32 hi/lo
// ============================================================
__global__ __launch_bounds__(256) void supports_kernel(const float* __restrict__ E) {
    __shared__ float vals[NN];
    __shared__ float red[256];
    const int n = blockIdx.x;
    const int tid = threadIdx.x;

    float en[ND];
#pragma unroll
    for (int d = 0; d < ND; d++) en[d] = E[n * ND + d];

    float lmax = -1e30f;
    for (int m = tid; m < NN; m += 256) {
        float v = 0.f;
#pragma unroll
        for (int d = 0; d < ND; d++) v = fmaf(en[d], E[m * ND + d], v);
        v = fmaxf(v, 0.f);
        vals[m] = v;
        lmax = fmaxf(lmax, v);
    }
    red[tid] = lmax; __syncthreads();
    for (int s = 128; s > 0; s >>= 1) { if (tid < s) red[tid] = fmaxf(red[tid], red[tid + s]); __syncthreads(); }
    const float gmax = red[0]; __syncthreads();

    float lsum = 0.f;
    for (int m = tid; m < NN; m += 256) {
        float e = expf(vals[m] - gmax);
        vals[m] = e; lsum += e;
    }
    red[tid] = lsum; __syncthreads();
    for (int s = 128; s > 0; s >>= 1) { if (tid < s) red[tid] += red[tid + s]; __syncthreads(); }
    const float inv = 1.f / red[0];
    for (int m = tid; m < NN; m += 256) {
        float v = vals[m] * inv;
        float hi = tf32r(v);
        g_Shi[n * NN + m] = hi;
        g_Slo[n * NN + m] = tf32r(v - hi);
    }
}

// ============================================================
// Xq builder: Xq[j = b*64+c][m] = x[b][m][c], split hi/lo
// ============================================================
__global__ __launch_bounds__(256) void xq_kernel(const float* __restrict__ x) {
    __shared__ float sm[64 * 33];
    const int m0 = blockIdx.x * 32;
    const int b  = blockIdx.y;
    const int t  = threadIdx.x;
#pragma unroll
    for (int p = 0; p < 8; p++) {
        int e = t + 256 * p;
        int r = e >> 6, c = e & 63;
        sm[c * 33 + r] = x[(size_t)b * (NN * NC) + (size_t)(m0 + r) * NC + c];
    }
    __syncthreads();
#pragma unroll
    for (int p = 0; p < 8; p++) {
        int e = t + 256 * p;
        int c = e >> 5, r = e & 31;
        float v = sm[c * 33 + r];
        float hi = tf32r(v);
        size_t off = (size_t)(b * 64 + c) * NN + m0 + r;
        g_Xqhi[off] = hi;
        g_Xqlo[off] = tf32r(v - hi);
    }
}

// ============================================================
// weights: W[n, ki, o] = sum_d E[n,d] * Wp[d, ki, o]
// ============================================================
__global__ __launch_bounds__(256) void weights_kernel(const float* __restrict__ E,
                                                      const float* __restrict__ Wp) {
    __shared__ float Es[16][ND];
    const int e0 = blockIdx.x * 256;
    const int n0 = blockIdx.y * 16;
    const int tid = threadIdx.x;
    if (tid < 16 * ND) Es[tid / ND][tid % ND] = E[(n0 + tid / ND) * ND + (tid % ND)];
    __syncthreads();
    const int e = e0 + tid;
    float wp[ND];
#pragma unroll
    for (int d = 0; d < ND; d++) wp[d] = Wp[d * (KI * NC) + e];
#pragma unroll
    for (int nn = 0; nn < 16; nn++) {
        float acc = 0.f;
#pragma unroll
        for (int d = 0; d < ND; d++) acc = fmaf(Es[nn][d], wp[d], acc);
        g_W[(size_t)(n0 + nn) * (KI * NC) + e] = acc;
    }
}

// ============================================================
// 3xTF32 mma.sync GEMM: C[128x128] tile, K=2048, 3-stage cp.async.
//   Inner loop is TERM-OUTER: all hi*hi MMAs, then lo*hi, then hi*lo,
//   so same-accumulator MMAs are 16 apart (no RAW stalls on acc).
// ============================================================
#define STAGE_BYTES 65536
#define AHI_OFF 0
#define ALO_OFF 16384
#define BHI_OFF 32768
#define BLO_OFF 49152
#define GEMM_SMEM (3 * STAGE_BYTES)
#define NITER (NN / 32)   // 64

template <int MODE>
__global__ void __launch_bounds__(256, 1) gemm_tf32x3_kernel() {
    extern __shared__ float dsm[];
    const int t = threadIdx.x;
    const int l = t & 31;
    const int wid = t >> 5;
    const int wm = wid >> 2;       // 0..1  (m direction, 64 rows each)
    const int wn = wid & 3;        // 0..3  (n direction, 32 cols each)
    const int bm = blockIdx.y * 128;
    const int bn = blockIdx.x * 128;

    const float* Ah = g_Shi + (size_t)bm * NN;
    const float* Al = g_Slo + (size_t)bm * NN;
    const float* Bh = (MODE == 1 ? g_Xqhi : g_Y1qhi) + (size_t)bn * NN;
    const float* Bl = (MODE == 1 ? g_Xqlo : g_Y1qlo) + (size_t)bn * NN;

    const uint32_t sb0 = smem_u32(dsm);

    auto load_stage = [&](int s, int k0) {
        const uint32_t sb = sb0 + (uint32_t)s * STAGE_BYTES;
#pragma unroll
        for (int p = 0; p < 4; p++) {
            const int g = t + 256 * p;          // granule id (16B)
            const int row = g >> 3;
            const int c16 = g & 7;
            const int sw = c16 ^ (row & 7);     // XOR swizzle on 16B columns
            const uint32_t so = sb + (uint32_t)(row * 128 + sw * 16);
            const size_t go = (size_t)row * NN + k0 + c16 * 4;
            cpa16(so + AHI_OFF, Ah + go);
            cpa16(so + ALO_OFF, Al + go);
            cpa16(so + BHI_OFF, Bh + go);
            cpa16(so + BLO_OFF, Bl + go);
        }
        asm volatile("cp.async.commit_group;" ::: "memory");
    };

    float acc[4][4][4];
#pragma unroll
    for (int a = 0; a < 4; a++)
#pragma unroll
        for (int b = 0; b < 4; b++)
#pragma unroll
            for (int c = 0; c < 4; c++) acc[a][b][c] = 0.f;

    // ldmatrix lane geometry
    const int t4 = l >> 3;                       // subtile id 0..3
    const int l7 = l & 7;
    const int arow_in = ((t4 & 1) << 3) + l7;    // A: subtile row-group + row
    const int brow_in = ((t4 >> 1) << 3) + l7;   // B: subtile n-group + row
    const uint32_t abase = (uint32_t)((wm * 64 + arow_in) * 128);
    const uint32_t bbase = (uint32_t)((wn * 32 + brow_in) * 128);
    const int akg = t4 >> 1;                     // A k-group select within kstep
    const int bkg = t4 & 1;                      // B k-group select within kstep

    load_stage(0, 0);
    load_stage(1, 32);

    for (int i = 0; i < NITER; i++) {
        asm volatile("cp.async.wait_group 1;" ::: "memory");
        __syncthreads();
        if (i + 2 < NITER) load_stage((i + 2) % 3, (i + 2) * 32);
        const uint32_t sb = sb0 + (uint32_t)(i % 3) * STAGE_BYTES;
#pragma unroll
        for (int ks = 0; ks < 4; ks++) {
            const uint32_t xa = (uint32_t)(((ks * 2 + akg) ^ l7) << 4);
            const uint32_t xb = (uint32_t)(((ks * 2 + bkg) ^ l7) << 4);
            uint32_t ah[4][4], al[4][4];
            uint32_t bhf[2][4], blf[2][4];

            // --- load hi fragments ---
#pragma unroll
            for (int mt = 0; mt < 4; mt++)
                LDSM4(ah[mt], sb + abase + (uint32_t)(mt * 16 * 128) + xa + AHI_OFF);
#pragma unroll
            for (int nh = 0; nh < 2; nh++)
                LDSM4(bhf[nh], sb + bbase + (uint32_t)(nh * 16 * 128) + xb + BHI_OFF);

            // --- term 1: hi*hi (16 MMAs, distinct accs) ---
#pragma unroll
            for (int mt = 0; mt < 4; mt++)
#pragma unroll
                for (int n8 = 0; n8 < 4; n8++) {
                    const int nh = n8 >> 1, q = (n8 & 1) * 2;
                    MMA_TF32(acc[mt][n8], ah[mt], bhf[nh][q], bhf[nh][q + 1]);
                }

            // --- load A lo, then term 2: lo*hi ---
#pragma unroll
            for (int mt = 0; mt < 4; mt++)
                LDSM4(al[mt], sb + abase + (uint32_t)(mt * 16 * 128) + xa + ALO_OFF);
#pragma unroll
            for (int mt = 0; mt < 4; mt++)
#pragma unroll
                for (int n8 = 0; n8 < 4; n8++) {
                    const int nh = n8 >> 1, q = (n8 & 1) * 2;
                    MMA_TF32(acc[mt][n8], al[mt], bhf[nh][q], bhf[nh][q + 1]);
                }

            // --- load B lo, then term 3: hi*lo ---
#pragma unroll
            for (int nh = 0; nh < 2; nh++)
                LDSM4(blf[nh], sb + bbase + (uint32_t)(nh * 16 * 128) + xb + BLO_OFF);
#pragma unroll
            for (int mt = 0; mt < 4; mt++)
#pragma unroll
                for (int n8 = 0; n8 < 4; n8++) {
                    const int nh = n8 >> 1, q = (n8 & 1) * 2;
                    MMA_TF32(acc[mt][n8], ah[mt], blf[nh][q], blf[nh][q + 1]);
                }
        }
    }

    // ---------------- epilogue ----------------
    float* Ynm = (MODE == 1) ? g_Y1nm : g_Y2nm;
    const int lm = l >> 2;
    const int lc = (l & 3) << 1;
#pragma unroll
    for (int mt = 0; mt < 4; mt++)
#pragma unroll
        for (int n8 = 0; n8 < 4; n8++) {
            const int r = bm + wm * 64 + mt * 16 + lm;
            const int col = bn + wn * 32 + n8 * 8 + lc;
            *(float2*)&Ynm[(size_t)r * NJ + col] =
                make_float2(acc[mt][n8][0], acc[mt][n8][1]);
            *(float2*)&Ynm[(size_t)(r + 8) * NJ + col] =
                make_float2(acc[mt][n8][2], acc[mt][n8][3]);
        }

    if (MODE == 1) {
        // transpose tile via smem (pitch 132), then coalesced hi/lo stores
        __syncthreads();
#pragma unroll
        for (int mt = 0; mt < 4; mt++)
#pragma unroll
            for (int n8 = 0; n8 < 4; n8++) {
                const int jl = wn * 32 + n8 * 8 + lc;
                const int ml = wm * 64 + mt * 16 + lm;
                dsm[jl * 132 + ml]           = acc[mt][n8][0];
                dsm[(jl + 1) * 132 + ml]     = acc[mt][n8][1];
                dsm[jl * 132 + ml + 8]       = acc[mt][n8][2];
                dsm[(jl + 1) * 132 + ml + 8] = acc[mt][n8][3];
            }
        __syncthreads();
#pragma unroll
        for (int it = 0; it < 16; it++) {
            const int j = wid * 16 + it;
            const int m4 = l * 4;
            const float4 v = *(const float4*)&dsm[j * 132 + m4];
            float4 hi, lo;
            hi.x = tf32r(v.x); lo.x = tf32r(v.x - hi.x);
            hi.y = tf32r(v.y); lo.y = tf32r(v.y - hi.y);
            hi.z = tf32r(v.z); lo.z = tf32r(v.z - hi.z);
            hi.w = tf32r(v.w); lo.w = tf32r(v.w - hi.w);
            const size_t off = (size_t)(bn + j) * NN + bm + m4;
            *(float4*)&g_Y1qhi[off] = hi;
            *(float4*)&g_Y1qlo[off] = lo;
        }
    }
}

// ============================================================
// output: per node n, out[b,n,o] = A_n[b,ki] @ W_n[ki,o] + bias_n[o]
// ============================================================
__global__ __launch_bounds__(256) void output_kernel(const float* __restrict__ x,
                                                     const float* __restrict__ E,
                                                     const float* __restrict__ bp,
                                                     float* __restrict__ out) {
    extern __shared__ float sm[];
    float* As = sm;                 // 192 * 65
    float* Ws = sm + KI * 65;       // 192 * 64

    const int n = blockIdx.x;
    const int tid = threadIdx.x;

    for (int idx = tid; idx < NJ; idx += 256) {
        const int b = idx >> 6;
        const int i = idx & 63;
        const float xv = x[(size_t)b * (NN * NC) + n * NC + i];
        const float y1 = g_Y1nm[(size_t)n * NJ + idx];
        const float y2 = g_Y2nm[(size_t)n * NJ + idx];
        As[(i)       * 65 + b] = xv;
        As[(64 + i)  * 65 + b] = y1;
        As[(128 + i) * 65 + b] = 2.f * y2 - xv;
    }
    const float* Wrow = &g_W[(size_t)n * (KI * NC)];
    for (int idx = tid * 4; idx < KI * NC; idx += 1024)
        *(float4*)&Ws[idx] = *(const float4*)&Wrow[idx];
    __syncthreads();

    const int o0 = (tid % 16) * 4;
    const int b0 = (tid / 16) * 4;
    float acc[4][4] = {};
#pragma unroll 4
    for (int kk = 0; kk < KI; kk++) {
        const float a0 = As[kk * 65 + b0 + 0];
        const float a1 = As[kk * 65 + b0 + 1];
        const float a2 = As[kk * 65 + b0 + 2];
        const float a3 = As[kk * 65 + b0 + 3];
        const float4 w = *(const float4*)&Ws[kk * 64 + o0];
        acc[0][0] = fmaf(a0, w.x, acc[0][0]); acc[0][1] = fmaf(a0, w.y, acc[0][1]);
        acc[0][2] = fmaf(a0, w.z, acc[0][2]); acc[0][3] = fmaf(a0, w.w, acc[0][3]);
        acc[1][0] = fmaf(a1, w.x, acc[1][0]); acc[1][1] = fmaf(a1, w.y, acc[1][1]);
        acc[1][2] = fmaf(a1, w.z, acc[1][2]); acc[1][3] = fmaf(a1, w.w, acc[1][3]);
        acc[2][0] = fmaf(a2, w.x, acc[2][0]); acc[2][1] = fmaf(a2, w.y, acc[2][1]);
        acc[2][2] = fmaf(a2, w.z, acc[2][2]); acc[2][3] = fmaf(a2, w.w, acc[2][3]);
        acc[3][0] = fmaf(a3, w.x, acc[3][0]); acc[3][1] = fmaf(a3, w.y, acc[3][1]);
        acc[3][2] = fmaf(a3, w.z, acc[3][2]); acc[3][3] = fmaf(a3, w.w, acc[3][3]);
    }

    float bias[4];
#pragma unroll
    for (int oo = 0; oo < 4; oo++) {
        float s = 0.f;
#pragma unroll
        for (int d = 0; d < ND; d++) s = fmaf(E[n * ND + d], bp[d * NC + o0 + oo], s);
        bias[oo] = s;
    }

#pragma unroll
    for (int bb = 0; bb < 4; bb++) {
        float4 v = make_float4(acc[bb][0] + bias[0], acc[bb][1] + bias[1],
                               acc[bb][2] + bias[2], acc[bb][3] + bias[3]);
        *(float4*)&out[(size_t)(b0 + bb) * (NN * NC) + n * NC + o0] = v;
    }
}

// ============================================================
extern "C" void kernel_launch(void* const* d_in, const int* in_sizes, int n_in,
                              void* d_out, int out_size) {
    (void)in_sizes; (void)n_in; (void)out_size;
    const float* x  = (const float*)d_in[0];
    const float* E  = (const float*)d_in[1];
    const float* Wp = (const float*)d_in[2];
    const float* bp = (const float*)d_in[3];
    float* out = (float*)d_out;

    const int kOutSmem = (KI * 65 + KI * NC) * (int)sizeof(float);
    cudaFuncSetAttribute(output_kernel, cudaFuncAttributeMaxDynamicSharedMemorySize, kOutSmem);
    cudaFuncSetAttribute(gemm_tf32x3_kernel<1>, cudaFuncAttributeMaxDynamicSharedMemorySize, GEMM_SMEM);
    cudaFuncSetAttribute(gemm_tf32x3_kernel<2>, cudaFuncAttributeMaxDynamicSharedMemorySize, GEMM_SMEM);

    supports_kernel<<<NN, 256>>>(E);
    xq_kernel<<<dim3(NN / 32, NB), 256>>>(x);
    weights_kernel<<<dim3((KI * NC) / 256, NN / 16), 256>>>(E, Wp);

    dim3 ggrid(NJ / 128, NN / 128);   // (32, 16)
    gemm_tf32x3_kernel<1><<<ggrid, 256, GEMM_SMEM>>>();
    gemm_tf32x3_kernel<2><<<ggrid, 256, GEMM_SMEM>>>();

    output_kernel<<<NN, 256, kOutSmem>>>(x, E, bp, out);
}

// round 5
// speedup vs baseline: 2.5037x; 1.6578x over previous
#include <cuda_runtime.h>
#include <cuda_bf16.h>
#include <math.h>
#include <stdint.h>

#define NB 64
#define NN 2048
#define NC 64
#define ND 10
#define NJ 4096          // NB*NC
#define KI 192           // cheb_k * C_IN

// ------------------ scratch (static device globals) ------------------
__device__ __nv_bfloat16 g_Shi [NN * NN];
__device__ __nv_bfloat16 g_Slo [NN * NN];
__device__ __nv_bfloat16 g_Xqhi[(size_t)NJ * NN];   // [j][m]
__device__ __nv_bfloat16 g_Xqlo[(size_t)NJ * NN];
__device__ __nv_bfloat16 g_Y1qhi[(size_t)NJ * NN];  // [j][m]
__device__ __nv_bfloat16 g_Y1qlo[(size_t)NJ * NN];
__device__ float g_Y1nm[(size_t)NN * NJ];           // [n][j]
__device__ float g_Y2nm[(size_t)NN * NJ];
__device__ float g_W   [(size_t)NN * KI * NC];

// ------------------ helpers ------------------
__device__ __forceinline__ uint32_t smem_u32(const void* p) {
    uint32_t a;
    asm("{ .reg .u64 t; cvta.to.shared.u64 t, %1; cvt.u32.u64 %0, t; }" : "=r"(a) : "l"(p));
    return a;
}
__device__ __forceinline__ void cpa16(uint32_t s, const void* g) {
    asm volatile("cp.async.cg.shared.global [%0], [%1], 16;" :: "r"(s), "l"(g));
}
__device__ __forceinline__ void bf16_split(float v, __nv_bfloat16& hi, __nv_bfloat16& lo) {
    hi = __float2bfloat16(v);
    lo = __float2bfloat16(v - __bfloat162float(hi));
}

#define LDSM4(r, a) \
    asm volatile("ldmatrix.sync.aligned.m8n8.x4.shared.b16 {%0,%1,%2,%3}, [%4];" \
        : "=r"((r)[0]), "=r"((r)[1]), "=r"((r)[2]), "=r"((r)[3]) : "r"(a))

#define MMA_BF16(c, a, b0, b1) \
    asm volatile("mma.sync.aligned.m16n8k16.row.col.f32.bf16.bf16.f32 " \
        "{%0,%1,%2,%3}, {%4,%5,%6,%7}, {%8,%9}, {%0,%1,%2,%3};" \
        : "+f"((c)[0]), "+f"((c)[1]), "+f"((c)[2]), "+f"((c)[3]) \
        : "r"((a)[0]), "r"((a)[1]), "r"((a)[2]), "r"((a)[3]), "r"(b0), "r"(b1))

// ============================================================
// supports: S[n,:] = softmax(relu(E[n]·E[m])), split bf16 hi/lo
// ============================================================
__global__ __launch_bounds__(256) void supports_kernel(const float* __restrict__ E) {
    __shared__ float vals[NN];
    __shared__ float red[256];
    const int n = blockIdx.x;
    const int tid = threadIdx.x;

    float en[ND];
#pragma unroll
    for (int d = 0; d < ND; d++) en[d] = E[n * ND + d];

    float lmax = -1e30f;
    for (int m = tid; m < NN; m += 256) {
        float v = 0.f;
#pragma unroll
        for (int d = 0; d < ND; d++) v = fmaf(en[d], E[m * ND + d], v);
        v = fmaxf(v, 0.f);
        vals[m] = v;
        lmax = fmaxf(lmax, v);
    }
    red[tid] = lmax; __syncthreads();
    for (int s = 128; s > 0; s >>= 1) { if (tid < s) red[tid] = fmaxf(red[tid], red[tid + s]); __syncthreads(); }
    const float gmax = red[0]; __syncthreads();

    float lsum = 0.f;
    for (int m = tid; m < NN; m += 256) {
        float e = expf(vals[m] - gmax);
        vals[m] = e; lsum += e;
    }
    red[tid] = lsum; __syncthreads();
    for (int s = 128; s > 0; s >>= 1) { if (tid < s) red[tid] += red[tid + s]; __syncthreads(); }
    const float inv = 1.f / red[0];
    for (int m = tid; m < NN; m += 256) {
        float v = vals[m] * inv;
        __nv_bfloat16 hi, lo; bf16_split(v, hi, lo);
        g_Shi[n * NN + m] = hi;
        g_Slo[n * NN + m] = lo;
    }
}

// ============================================================
// Xq builder: Xq[j = b*64+c][m] = x[b][m][c], split bf16 hi/lo
// ============================================================
__global__ __launch_bounds__(256) void xq_kernel(const float* __restrict__ x) {
    __shared__ float sm[64 * 33];
    const int m0 = blockIdx.x * 32;
    const int b  = blockIdx.y;
    const int t  = threadIdx.x;
#pragma unroll
    for (int p = 0; p < 8; p++) {
        int e = t + 256 * p;
        int r = e >> 6, c = e & 63;
        sm[c * 33 + r] = x[(size_t)b * (NN * NC) + (size_t)(m0 + r) * NC + c];
    }
    __syncthreads();
#pragma unroll
    for (int p = 0; p < 8; p++) {
        int e = t + 256 * p;
        int c = e >> 5, r = e & 31;
        float v = sm[c * 33 + r];
        __nv_bfloat16 hi, lo; bf16_split(v, hi, lo);
        size_t off = (size_t)(b * 64 + c) * NN + m0 + r;
        g_Xqhi[off] = hi;
        g_Xqlo[off] = lo;
    }
}

// ============================================================
// weights: W[n, ki, o] = sum_d E[n,d] * Wp[d, ki, o]
// ============================================================
__global__ __launch_bounds__(256) void weights_kernel(const float* __restrict__ E,
                                                      const float* __restrict__ Wp) {
    __shared__ float Es[16][ND];
    const int e0 = blockIdx.x * 256;
    const int n0 = blockIdx.y * 16;
    const int tid = threadIdx.x;
    if (tid < 16 * ND) Es[tid / ND][tid % ND] = E[(n0 + tid / ND) * ND + (tid % ND)];
    __syncthreads();
    const int e = e0 + tid;
    float wp[ND];
#pragma unroll
    for (int d = 0; d < ND; d++) wp[d] = Wp[d * (KI * NC) + e];
#pragma unroll
    for (int nn = 0; nn < 16; nn++) {
        float acc = 0.f;
#pragma unroll
        for (int d = 0; d < ND; d++) acc = fmaf(Es[nn][d], wp[d], acc);
        g_W[(size_t)(n0 + nn) * (KI * NC) + e] = acc;
    }
}

// ============================================================
// 3xBF16 mma.sync GEMM (m16n8k16): C[128x128] tile, K=2048.
//   BK=64 bf16 per stage (128B rows), 3-stage cp.async.
//   Terms: hi*hi + lo*hi + hi*lo (lo*lo dropped, ~1.5e-5).
// ============================================================
#define STAGE_BYTES 65536
#define AHI_OFF 0
#define ALO_OFF 16384
#define BHI_OFF 32768
#define BLO_OFF 49152
#define GEMM_SMEM (3 * STAGE_BYTES)
#define NITER (NN / 64)   // 32

template <int MODE>
__global__ void __launch_bounds__(256, 1) gemm_bf16x3_kernel() {
    extern __shared__ float dsm[];
    const int t = threadIdx.x;
    const int l = t & 31;
    const int wid = t >> 5;
    const int wm = wid >> 2;       // 0..1  (m direction, 64 rows each)
    const int wn = wid & 3;        // 0..3  (n direction, 32 cols each)
    const int bm = blockIdx.y * 128;
    const int bn = blockIdx.x * 128;

    const __nv_bfloat16* Ah = g_Shi + (size_t)bm * NN;
    const __nv_bfloat16* Al = g_Slo + (size_t)bm * NN;
    const __nv_bfloat16* Bh = (MODE == 1 ? g_Xqhi : g_Y1qhi) + (size_t)bn * NN;
    const __nv_bfloat16* Bl = (MODE == 1 ? g_Xqlo : g_Y1qlo) + (size_t)bn * NN;

    const uint32_t sb0 = smem_u32(dsm);

    auto load_stage = [&](int s, int k0) {
        const uint32_t sb = sb0 + (uint32_t)s * STAGE_BYTES;
#pragma unroll
        for (int p = 0; p < 4; p++) {
            const int g = t + 256 * p;          // granule id (16B = 8 bf16)
            const int row = g >> 3;
            const int c16 = g & 7;
            const int sw = c16 ^ (row & 7);     // XOR swizzle on 16B columns
            const uint32_t so = sb + (uint32_t)(row * 128 + sw * 16);
            const size_t go = (size_t)row * NN + k0 + c16 * 8;
            cpa16(so + AHI_OFF, Ah + go);
            cpa16(so + ALO_OFF, Al + go);
            cpa16(so + BHI_OFF, Bh + go);
            cpa16(so + BLO_OFF, Bl + go);
        }
        asm volatile("cp.async.commit_group;" ::: "memory");
    };

    float acc[4][4][4];
#pragma unroll
    for (int a = 0; a < 4; a++)
#pragma unroll
        for (int b = 0; b < 4; b++)
#pragma unroll
            for (int c = 0; c < 4; c++) acc[a][b][c] = 0.f;

    // ldmatrix lane geometry (x4: lanes 0-7/8-15/16-23/24-31 -> 4 matrices)
    const int t4 = l >> 3;
    const int l7 = l & 7;
    const int arow_in = ((t4 & 1) << 3) + l7;    // A: m-subrow
    const int brow_in = ((t4 >> 1) << 3) + l7;   // B: n-subrow
    const uint32_t abase = (uint32_t)((wm * 64 + arow_in) * 128);
    const uint32_t bbase = (uint32_t)((wn * 32 + brow_in) * 128);
    const int akg = t4 >> 1;                     // A k-granule select (k16 halves)
    const int bkg = t4 & 1;                      // B k-granule select

    load_stage(0, 0);
    load_stage(1, 64);

    for (int i = 0; i < NITER; i++) {
        asm volatile("cp.async.wait_group 1;" ::: "memory");
        __syncthreads();
        if (i + 2 < NITER) load_stage((i + 2) % 3, (i + 2) * 64);
        const uint32_t sb = sb0 + (uint32_t)(i % 3) * STAGE_BYTES;
#pragma unroll
        for (int ks = 0; ks < 4; ks++) {         // k16 steps within BK=64
            const uint32_t xa = (uint32_t)(((ks * 2 + akg) ^ l7) << 4);
            const uint32_t xb = (uint32_t)(((ks * 2 + bkg) ^ l7) << 4);
            uint32_t ah[4][4], al[4][4];
            uint32_t bhf[2][4], blf[2][4];

#pragma unroll
            for (int mt = 0; mt < 4; mt++)
                LDSM4(ah[mt], sb + abase + (uint32_t)(mt * 16 * 128) + xa + AHI_OFF);
#pragma unroll
            for (int nh = 0; nh < 2; nh++)
                LDSM4(bhf[nh], sb + bbase + (uint32_t)(nh * 16 * 128) + xb + BHI_OFF);

            // term 1: hi*hi
#pragma unroll
            for (int mt = 0; mt < 4; mt++)
#pragma unroll
                for (int n8 = 0; n8 < 4; n8++) {
                    const int nh = n8 >> 1, q = (n8 & 1) * 2;
                    MMA_BF16(acc[mt][n8], ah[mt], bhf[nh][q], bhf[nh][q + 1]);
                }

            // term 2: lo*hi
#pragma unroll
            for (int mt = 0; mt < 4; mt++)
                LDSM4(al[mt], sb + abase + (uint32_t)(mt * 16 * 128) + xa + ALO_OFF);
#pragma unroll
            for (int mt = 0; mt < 4; mt++)
#pragma unroll
                for (int n8 = 0; n8 < 4; n8++) {
                    const int nh = n8 >> 1, q = (n8 & 1) * 2;
                    MMA_BF16(acc[mt][n8], al[mt], bhf[nh][q], bhf[nh][q + 1]);
                }

            // term 3: hi*lo
#pragma unroll
            for (int nh = 0; nh < 2; nh++)
                LDSM4(blf[nh], sb + bbase + (uint32_t)(nh * 16 * 128) + xb + BLO_OFF);
#pragma unroll
            for (int mt = 0; mt < 4; mt++)
#pragma unroll
                for (int n8 = 0; n8 < 4; n8++) {
                    const int nh = n8 >> 1, q = (n8 & 1) * 2;
                    MMA_BF16(acc[mt][n8], ah[mt], blf[nh][q], blf[nh][q + 1]);
                }
        }
    }

    // ---------------- epilogue ----------------
    float* Ynm = (MODE == 1) ? g_Y1nm : g_Y2nm;
    const int lm = l >> 2;
    const int lc = (l & 3) << 1;
#pragma unroll
    for (int mt = 0; mt < 4; mt++)
#pragma unroll
        for (int n8 = 0; n8 < 4; n8++) {
            const int r = bm + wm * 64 + mt * 16 + lm;
            const int col = bn + wn * 32 + n8 * 8 + lc;
            *(float2*)&Ynm[(size_t)r * NJ + col] =
                make_float2(acc[mt][n8][0], acc[mt][n8][1]);
            *(float2*)&Ynm[(size_t)(r + 8) * NJ + col] =
                make_float2(acc[mt][n8][2], acc[mt][n8][3]);
        }

    if (MODE == 1) {
        // transpose tile via smem (pitch 132), then coalesced bf16 hi/lo stores
        __syncthreads();
#pragma unroll
        for (int mt = 0; mt < 4; mt++)
#pragma unroll
            for (int n8 = 0; n8 < 4; n8++) {
                const int jl = wn * 32 + n8 * 8 + lc;
                const int ml = wm * 64 + mt * 16 + lm;
                dsm[jl * 132 + ml]           = acc[mt][n8][0];
                dsm[(jl + 1) * 132 + ml]     = acc[mt][n8][1];
                dsm[jl * 132 + ml + 8]       = acc[mt][n8][2];
                dsm[(jl + 1) * 132 + ml + 8] = acc[mt][n8][3];
            }
        __syncthreads();
#pragma unroll
        for (int it = 0; it < 16; it++) {
            const int j = wid * 16 + it;
            const int m4 = l * 4;
            const float4 v = *(const float4*)&dsm[j * 132 + m4];
            __nv_bfloat16 h0, h1, h2, h3, o0, o1, o2, o3;
            bf16_split(v.x, h0, o0);
            bf16_split(v.y, h1, o1);
            bf16_split(v.z, h2, o2);
            bf16_split(v.w, h3, o3);
            const size_t off = (size_t)(bn + j) * NN + bm + m4;
            __nv_bfloat162 hp0 = make_bfloat162(h0, h1), hp1 = make_bfloat162(h2, h3);
            __nv_bfloat162 lp0 = make_bfloat162(o0, o1), lp1 = make_bfloat162(o2, o3);
            uint2 hw, lw;
            hw.x = *(uint32_t*)&hp0; hw.y = *(uint32_t*)&hp1;
            lw.x = *(uint32_t*)&lp0; lw.y = *(uint32_t*)&lp1;
            *(uint2*)&g_Y1qhi[off] = hw;
            *(uint2*)&g_Y1qlo[off] = lw;
        }
    }
}

// ============================================================
// output: per node n, out[b,n,o] = A_n[b,ki] @ W_n[ki,o] + bias_n[o]
// ============================================================
__global__ __launch_bounds__(256) void output_kernel(const float* __restrict__ x,
                                                     const float* __restrict__ E,
                                                     const float* __restrict__ bp,
                                                     float* __restrict__ out) {
    extern __shared__ float sm[];
    float* As = sm;                 // 192 * 65
    float* Ws = sm + KI * 65;       // 192 * 64

    const int n = blockIdx.x;
    const int tid = threadIdx.x;

    for (int idx = tid; idx < NJ; idx += 256) {
        const int b = idx >> 6;
        const int i = idx & 63;
        const float xv = x[(size_t)b * (NN * NC) + n * NC + i];
        const float y1 = g_Y1nm[(size_t)n * NJ + idx];
        const float y2 = g_Y2nm[(size_t)n * NJ + idx];
        As[(i)       * 65 + b] = xv;
        As[(64 + i)  * 65 + b] = y1;
        As[(128 + i) * 65 + b] = 2.f * y2 - xv;
    }
    const float* Wrow = &g_W[(size_t)n * (KI * NC)];
    for (int idx = tid * 4; idx < KI * NC; idx += 1024)
        *(float4*)&Ws[idx] = *(const float4*)&Wrow[idx];
    __syncthreads();

    const int o0 = (tid % 16) * 4;
    const int b0 = (tid / 16) * 4;
    float acc[4][4] = {};
#pragma unroll 4
    for (int kk = 0; kk < KI; kk++) {
        const float a0 = As[kk * 65 + b0 + 0];
        const float a1 = As[kk * 65 + b0 + 1];
        const float a2 = As[kk * 65 + b0 + 2];
        const float a3 = As[kk * 65 + b0 + 3];
        const float4 w = *(const float4*)&Ws[kk * 64 + o0];
        acc[0][0] = fmaf(a0, w.x, acc[0][0]); acc[0][1] = fmaf(a0, w.y, acc[0][1]);
        acc[0][2] = fmaf(a0, w.z, acc[0][2]); acc[0][3] = fmaf(a0, w.w, acc[0][3]);
        acc[1][0] = fmaf(a1, w.x, acc[1][0]); acc[1][1] = fmaf(a1, w.y, acc[1][1]);
        acc[1][2] = fmaf(a1, w.z, acc[1][2]); acc[1][3] = fmaf(a1, w.w, acc[1][3]);
        acc[2][0] = fmaf(a2, w.x, acc[2][0]); acc[2][1] = fmaf(a2, w.y, acc[2][1]);
        acc[2][2] = fmaf(a2, w.z, acc[2][2]); acc[2][3] = fmaf(a2, w.w, acc[2][3]);
        acc[3][0] = fmaf(a3, w.x, acc[3][0]); acc[3][1] = fmaf(a3, w.y, acc[3][1]);
        acc[3][2] = fmaf(a3, w.z, acc[3][2]); acc[3][3] = fmaf(a3, w.w, acc[3][3]);
    }

    float bias[4];
#pragma unroll
    for (int oo = 0; oo < 4; oo++) {
        float s = 0.f;
#pragma unroll
        for (int d = 0; d < ND; d++) s = fmaf(E[n * ND + d], bp[d * NC + o0 + oo], s);
        bias[oo] = s;
    }

#pragma unroll
    for (int bb = 0; bb < 4; bb++) {
        float4 v = make_float4(acc[bb][0] + bias[0], acc[bb][1] + bias[1],
                               acc[bb][2] + bias[2], acc[bb][3] + bias[3]);
        *(float4*)&out[(size_t)(b0 + bb) * (NN * NC) + n * NC + o0] = v;
    }
}

// ============================================================
extern "C" void kernel_launch(void* const* d_in, const int* in_sizes, int n_in,
                              void* d_out, int out_size) {
    (void)in_sizes; (void)n_in; (void)out_size;
    const float* x  = (const float*)d_in[0];
    const float* E  = (const float*)d_in[1];
    const float* Wp = (const float*)d_in[2];
    const float* bp = (const float*)d_in[3];
    float* out = (float*)d_out;

    const int kOutSmem = (KI * 65 + KI * NC) * (int)sizeof(float);
    cudaFuncSetAttribute(output_kernel, cudaFuncAttributeMaxDynamicSharedMemorySize, kOutSmem);
    cudaFuncSetAttribute(gemm_bf16x3_kernel<1>, cudaFuncAttributeMaxDynamicSharedMemorySize, GEMM_SMEM);
    cudaFuncSetAttribute(gemm_bf16x3_kernel<2>, cudaFuncAttributeMaxDynamicSharedMemorySize, GEMM_SMEM);

    supports_kernel<<<NN, 256>>>(E);
    xq_kernel<<<dim3(NN / 32, NB), 256>>>(x);
    weights_kernel<<<dim3((KI * NC) / 256, NN / 16), 256>>>(E, Wp);

    dim3 ggrid(NJ / 128, NN / 128);   // (32, 16)
    gemm_bf16x3_kernel<1><<<ggrid, 256, GEMM_SMEM>>>();
    gemm_bf16x3_kernel<2><<<ggrid, 256, GEMM_SMEM>>>();

    output_kernel<<<NN, 256, kOutSmem>>>(x, E, bp, out);
}